// round 9
// baseline (speedup 1.0000x reference)
#include <cuda_runtime.h>
#include <cub/cub.cuh>
#include <stdint.h>

// Voxel key space: ((b*128 + qx)*128 + qy)*64 + qt  with b<16, qx<128, qy<128, qt<64
//   = b*2^20 + qx*2^13 + qy*2^6 + qt  in [0, 2^24)
#define NVOX (1 << 24)
#define NMAX 1000000
#define EMAX 8000000
#define SENT 0xFFFFFFFFFFULL  // > any packed edge key ((s<<20)|d with s,d < 2^20)

__device__ unsigned g_flag[NVOX];               // voxel occupancy flags; reused as edge-unique flags
__device__ unsigned g_pref[NVOX];               // exclusive prefix; reused for edge ranks
__device__ int g_vox[NMAX];
__device__ int g_inv[NMAX];
__device__ unsigned long long g_keys[EMAX];
__device__ unsigned long long g_keys2[EMAX];
__device__ unsigned g_U;                        // number of unique voxels
// 64 MB CUB temp — VALIDATED: 8 MB temp crashed the container both times
// (onesweep lookback-state overflow past the symbol); 64 MB ran clean.
__device__ __align__(256) unsigned char g_temp[64u << 20];

// order-preserving float <-> uint encoding for atomicMax-based segment max
static __device__ __forceinline__ unsigned encf(float f) {
    unsigned u = __float_as_uint(f);
    return (u & 0x80000000u) ? ~u : (u | 0x80000000u);
}
static __device__ __forceinline__ float decf(unsigned u) {
    return __uint_as_float((u & 0x80000000u) ? (u & 0x7FFFFFFFu) : ~u);
}

__global__ void k_vox(const float* __restrict__ pos, const int* __restrict__ batch, int n) {
    int i = blockIdx.x * blockDim.x + threadIdx.x;
    if (i >= n) return;
    float px = pos[3 * i + 0];
    float py = pos[3 * i + 1];
    float pt = pos[3 * i + 2];
    // Match XLA's lowering of pos / POOL (constant divisor): multiply by the
    // ROUNDED reciprocal, RN(1/4000) = 0.00025f, single RN multiply.
    // IEEE division provably does NOT match: plain `/` and __fdiv_rn both gave
    // the identical rel_err 1.320483e-3, whose norm corresponds to ~2 flipped
    // boundary nodes x degree 16 — exactly the expected ulp-flip count for
    // reciprocal-multiply vs true division. 1/4 is exact either way.
    int qx = (int)floorf(__fmul_rn(px, 0.25f));
    int qy = (int)floorf(__fmul_rn(py, 0.25f));
    int qt = (int)floorf(__fmul_rn(pt, 0.00025f));
    int b = batch[i];
    int v = ((b * 128 + qx) * 128 + qy) * 64 + qt;
    g_vox[i] = v;
    g_flag[v] = 1u;
}

__global__ void k_inv(int n) {
    int i = blockIdx.x * blockDim.x + threadIdx.x;
    if (i >= n) return;
    g_inv[i] = (int)g_pref[g_vox[i]];
}

__global__ void k_fill_neg(float* __restrict__ p, int cnt) {
    int i = blockIdx.x * blockDim.x + threadIdx.x;
    if (i < cnt) p[i] = -1.0f;
}

__global__ void k_pool(const float* __restrict__ x, unsigned* __restrict__ outp, int tot, int F) {
    int t = blockIdx.x * blockDim.x + threadIdx.x;
    if (t >= tot) return;
    int node = t / F;
    int f = t - node * F;
    atomicMax(outp + g_inv[node] * F + f, encf(x[t]));
}

__global__ void k_decode(unsigned* __restrict__ outp, int tot, int F) {
    int t = blockIdx.x * blockDim.x + threadIdx.x;
    if (t >= tot) return;
    int r = t / F;
    float v = (r < (int)g_U) ? decf(outp[t]) : 0.0f;
    ((float*)outp)[t] = v;
}

__global__ void k_decomp(float* __restrict__ out_q, float* __restrict__ out_b,
                         float* __restrict__ out_e, int E) {
    int v = blockIdx.x * blockDim.x + threadIdx.x;
    if (v >= NVOX) return;
    unsigned fl = g_flag[v];
    if (v == NVOX - 1) g_U = g_pref[v] + fl;
    if (!fl) return;
    int r = (int)g_pref[v];
    out_q[3 * r + 0] = (float)((v >> 13) & 127);  // qx
    out_q[3 * r + 1] = (float)((v >> 6) & 127);   // qy
    out_q[3 * r + 2] = (float)(v & 63);           // qt
    out_b[r] = (float)(v >> 20);                  // batch
    // self-loop rows of ei_out
    out_e[2 * (E + r) + 0] = (float)r;
    out_e[2 * (E + r) + 1] = (float)r;
}

__global__ void k_ekey(const int* __restrict__ eidx, int E) {
    int e = blockIdx.x * blockDim.x + threadIdx.x;
    if (e >= E) return;
    int s = g_inv[eidx[2 * e + 0]];
    int d = g_inv[eidx[2 * e + 1]];
    // (s<<20)|d is order-isomorphic to s*N+d since d < N <= 2^20
    g_keys[e] = (s != d) ? ((((unsigned long long)s) << 20) | (unsigned)d) : SENT;
}

__global__ void k_eflag(const unsigned long long* __restrict__ sk, int E) {
    int e = blockIdx.x * blockDim.x + threadIdx.x;
    if (e >= E) return;
    unsigned long long k = sk[e];
    unsigned f = (k != SENT) && (e == 0 || sk[e - 1] != k);
    g_flag[e] = f;
}

__global__ void k_escatter(const unsigned long long* __restrict__ sk,
                           float* __restrict__ out_e, int E) {
    int e = blockIdx.x * blockDim.x + threadIdx.x;
    if (e >= E) return;
    if (!g_flag[e]) return;
    int r = (int)g_pref[e];
    unsigned long long k = sk[e];
    out_e[2 * r + 0] = (float)(unsigned)(k >> 20);
    out_e[2 * r + 1] = (float)(unsigned)(k & 0xFFFFFu);
}

extern "C" void kernel_launch(void* const* d_in, const int* in_sizes, int n_in,
                              void* d_out, int out_size) {
    const float* x = (const float*)d_in[0];
    const float* pos = (const float*)d_in[1];
    const int* eidx = (const int*)d_in[2];
    const int* batch = (const int*)d_in[3];

    int n = in_sizes[1] / 3;          // nodes
    int F = in_sizes[0] / n;          // feature dim
    int E = in_sizes[2] / 2;          // edges
    float* out = (float*)d_out;

    long long OFF_Q = (long long)n * F;             // uniq_qpos
    long long OFF_E = OFF_Q + 3LL * n;              // ei_out
    long long OFF_B = OFF_E + 2LL * (E + n);        // new_batch

    void *p_flag, *p_pref, *p_keys, *p_keys2, *p_temp;
    cudaGetSymbolAddress(&p_flag, g_flag);
    cudaGetSymbolAddress(&p_pref, g_pref);
    cudaGetSymbolAddress(&p_keys, g_keys);
    cudaGetSymbolAddress(&p_keys2, g_keys2);
    cudaGetSymbolAddress(&p_temp, g_temp);

    cudaStream_t s = 0;
    const int T = 256;

    // --- init ---
    cudaMemsetAsync(p_flag, 0, (size_t)NVOX * sizeof(unsigned), s);
    cudaMemsetAsync(d_out, 0, (size_t)n * F * sizeof(float), s);   // pooled region: below all encf() values
    {
        int cnt = out_size - (int)OFF_Q;   // qpos + edges + batch regions -> -1
        k_fill_neg<<<(cnt + T - 1) / T, T, 0, s>>>(out + OFF_Q, cnt);
    }

    // --- node path: voxel keys -> occupancy -> prefix ranks ---
    k_vox<<<(n + T - 1) / T, T, 0, s>>>(pos, batch, n);
    {
        size_t tb = 0;
        cub::DeviceScan::ExclusiveSum(nullptr, tb, (unsigned*)p_flag, (unsigned*)p_pref, NVOX, s);
        cub::DeviceScan::ExclusiveSum(p_temp, tb, (unsigned*)p_flag, (unsigned*)p_pref, NVOX, s);
    }
    k_inv<<<(n + T - 1) / T, T, 0, s>>>(n);
    k_decomp<<<(NVOX + T - 1) / T, T, 0, s>>>(out + OFF_Q, out + OFF_B, out + OFF_E, E);

    // --- pooled features: atomic segment-max + in-place decode ---
    {
        int tot = n * F;
        k_pool<<<(tot + T - 1) / T, T, 0, s>>>(x, (unsigned*)d_out, tot, F);
        k_decode<<<(tot + T - 1) / T, T, 0, s>>>((unsigned*)d_out, tot, F);
    }

    // --- edge path: remap -> 40-bit radix sort (DoubleBuffer) -> unique -> scatter ---
    k_ekey<<<(E + T - 1) / T, T, 0, s>>>(eidx, E);
    const unsigned long long* sorted;
    {
        cub::DoubleBuffer<unsigned long long> dk((unsigned long long*)p_keys,
                                                 (unsigned long long*)p_keys2);
        size_t tb = 0;
        cub::DeviceRadixSort::SortKeys(nullptr, tb, dk, E, 0, 40, s);
        // DoubleBuffer overload avoids the internal alt-keys copy; selector is
        // resolved host-side at capture time (fixed pass count) -> graph-safe.
        cub::DeviceRadixSort::SortKeys(p_temp, tb, dk, E, 0, 40, s);
        sorted = dk.Current();
    }
    k_eflag<<<(E + T - 1) / T, T, 0, s>>>(sorted, E);
    {
        size_t tb = 0;
        cub::DeviceScan::ExclusiveSum(nullptr, tb, (unsigned*)p_flag, (unsigned*)p_pref, E, s);
        cub::DeviceScan::ExclusiveSum(p_temp, tb, (unsigned*)p_flag, (unsigned*)p_pref, E, s);
    }
    k_escatter<<<(E + T - 1) / T, T, 0, s>>>(sorted, out + OFF_E, E);
}